// round 2
// baseline (speedup 1.0000x reference)
#include <cuda_runtime.h>
#include <math.h>

#define LROW 4096
#define SHLF 2048
#define NT 256

__global__ __launch_bounds__(NT, 2)
void bw_kernel(const float* __restrict__ x,
               const float* __restrict__ w1,
               const float* __restrict__ g1,
               const float* __restrict__ b1,
               const float* __restrict__ m1,
               const float* __restrict__ v1,
               const float* __restrict__ w2L,
               const float* __restrict__ w2H,
               const float* __restrict__ wskip,
               float* __restrict__ out)
{
    __shared__ __align__(16) float xs[LROW + 8];     // xs[t+4] = x[t], zero halo +/-3
    __shared__ __align__(16) float sumh[SHLF + 8];   // sumh[s+3] = h[2s]+h[2s+1]
    __shared__ __align__(16) float difh[SHLF + 8];   // difh[s+1] = h[2s]-h[2s+1]

    const int tid = threadIdx.x;
    const int bx  = blockIdx.x;
    const int b   = bx >> 6;
    const int cin = bx & 63;

    // ---- load x row (coalesced float4) ----
    const float4* xr  = (const float4*)(x + (((size_t)b * 64 + cin) << 12));
    float4*       xs4 = (float4*)(xs + 4);
    #pragma unroll
    for (int i = 0; i < LROW / 4 / NT; i++)
        xs4[tid + i * NT] = xr[tid + i * NT];
    if (tid < 4) { xs[tid] = 0.f; xs[LROW + 4 + tid] = 0.f; }
    if (tid < 8) {                      // halos of sumh/difh (interior rewritten later)
        sumh[tid] = 0.f; sumh[SHLF + tid] = 0.f;
        difh[tid] = 0.f; difh[SHLF + tid] = 0.f;
    }
    __syncthreads();

    const float ISQ2 = 0.70710678118654752f;

    #pragma unroll 1
    for (int oc = 0; oc < 2; oc++) {
        const int g = 2 * cin + oc;
        float cw[7], wl[7], wh[3];
        #pragma unroll
        for (int k = 0; k < 7; k++) cw[k] = __ldg(&w1[g * 7 + k]);
        #pragma unroll
        for (int k = 0; k < 7; k++) wl[k] = 0.5f * __ldg(&w2L[g * 7 + k]);
        #pragma unroll
        for (int k = 0; k < 3; k++) wh[k] = 0.5f * __ldg(&w2H[g * 3 + k]);
        const float scale = __ldg(&g1[g]) * rsqrtf(__ldg(&v1[g]) + 1e-5f);
        const float shift = __ldg(&b1[g]) - __ldg(&m1[g]) * scale;
        const float wsk   = __ldg(&wskip[g]);

        // ---- stage 1: h = leaky(gelu(bn(conv7(x)))) -> sumh/difh ----
        #pragma unroll
        for (int c = 0; c < 2; c++) {
            const int t0 = 8 * tid + 2048 * c;       // 8 h-elements per chunk
            float xw[16];
            {
                float4* xwv = (float4*)xw;
                const float4* src = (const float4*)(xs + t0);  // covers x[t0-4 .. t0+12)
                xwv[0] = src[0]; xwv[1] = src[1]; xwv[2] = src[2]; xwv[3] = src[3];
            }
            float hprev = 0.f;
            #pragma unroll
            for (int j = 0; j < 8; j++) {
                // h[t0+j] taps x[t0+j-3 .. t0+j+3] = xw[j+1 .. j+7]
                float acc = xw[j + 1] * cw[0];
                #pragma unroll
                for (int k = 1; k < 7; k++) acc = fmaf(xw[j + 1 + k], cw[k], acc);
                acc = fmaf(acc, scale, shift);
                float ge = 0.5f * acc * (1.f + erff(acc * ISQ2));   // exact gelu
                ge = (ge >= 0.f) ? ge : 0.01f * ge;                 // leaky
                if (j & 1) {
                    const int s = 4 * tid + 1024 * c + (j >> 1);
                    sumh[s + 3] = hprev + ge;
                    difh[s + 1] = hprev - ge;
                } else {
                    hprev = ge;
                }
            }
        }
        __syncthreads();

        // ---- stage 2: half-rate convs + merge + skip + leaky ----
        {
            const int s0 = 8 * tid;
            float su[16], dv[12], xk[16];
            {
                float4* v = (float4*)su;
                const float4* p = (const float4*)(sumh + s0);
                v[0] = p[0]; v[1] = p[1]; v[2] = p[2]; v[3] = p[3];
            }
            {
                float4* v = (float4*)dv;
                const float4* p = (const float4*)(difh + s0);
                v[0] = p[0]; v[1] = p[1]; v[2] = p[2];
            }
            {
                float4* v = (float4*)xk;
                const float4* p = (const float4*)(xs + 2 * s0 + 4);
                v[0] = p[0]; v[1] = p[1]; v[2] = p[2]; v[3] = p[3];
            }

            float4* orow = (float4*)(out + (((size_t)(b * 128 + g)) << 12) + 2 * s0);
            #pragma unroll
            for (int jj = 0; jj < 4; jj++) {
                float4 r;
                {
                    const int j = 2 * jj;
                    float yl = su[j] * wl[0];
                    #pragma unroll
                    for (int k = 1; k < 7; k++) yl = fmaf(su[j + k], wl[k], yl);
                    float yh = dv[j] * wh[0];
                    #pragma unroll
                    for (int k = 1; k < 3; k++) yh = fmaf(dv[j + k], wh[k], yh);
                    float oe = yl + yh + xk[2 * j] * wsk;
                    float oo = yl - yh + xk[2 * j + 1] * wsk;
                    r.x = (oe >= 0.f) ? oe : 0.01f * oe;
                    r.y = (oo >= 0.f) ? oo : 0.01f * oo;
                }
                {
                    const int j = 2 * jj + 1;
                    float yl = su[j] * wl[0];
                    #pragma unroll
                    for (int k = 1; k < 7; k++) yl = fmaf(su[j + k], wl[k], yl);
                    float yh = dv[j] * wh[0];
                    #pragma unroll
                    for (int k = 1; k < 3; k++) yh = fmaf(dv[j + k], wh[k], yh);
                    float oe = yl + yh + xk[2 * j] * wsk;
                    float oo = yl - yh + xk[2 * j + 1] * wsk;
                    r.z = (oe >= 0.f) ? oe : 0.01f * oe;
                    r.w = (oo >= 0.f) ? oo : 0.01f * oo;
                }
                orow[jj] = r;
            }
        }
        __syncthreads();
    }
}

extern "C" void kernel_launch(void* const* d_in, const int* in_sizes, int n_in,
                              void* d_out, int out_size)
{
    const float* x     = (const float*)d_in[0];
    const float* w1    = (const float*)d_in[1];
    const float* g1    = (const float*)d_in[2];
    const float* b1    = (const float*)d_in[3];
    const float* m1    = (const float*)d_in[4];
    const float* v1    = (const float*)d_in[5];
    const float* w2L   = (const float*)d_in[6];
    const float* w2H   = (const float*)d_in[7];
    const float* wskip = (const float*)d_in[8];
    float* out = (float*)d_out;

    const int B = in_sizes[0] >> 18;   // elements / (64*4096)
    bw_kernel<<<B * 64, NT>>>(x, w1, g1, b1, m1, v1, w2L, w2H, wskip, out);
}

// round 3
// speedup vs baseline: 1.4663x; 1.4663x over previous
#include <cuda_runtime.h>
#include <math.h>

#define NT 256

__global__ __launch_bounds__(NT, 3)
void bw_kernel(const float* __restrict__ x,
               const float* __restrict__ w1,
               const float* __restrict__ g1,
               const float* __restrict__ b1,
               const float* __restrict__ m1,
               const float* __restrict__ v1,
               const float* __restrict__ w2L,
               const float* __restrict__ w2H,
               const float* __restrict__ wskip,
               float* __restrict__ out)
{
    // xs[t+4] = x[t], t in [0,4096); zero halo +/-4
    __shared__ __align__(16) float xs[4096 + 16];
    // sh[s+5] = S[s] = h[2s]+h[2s+1]; zero halo so float2 reads start aligned+conflict-free
    __shared__ __align__(16) float sh[2064];
    // dh[s+1] = D[s] = h[2s]-h[2s+1]
    __shared__ __align__(16) float dh[2064];

    const int tid = threadIdx.x;
    const int b   = blockIdx.x >> 6;
    const int cin = blockIdx.x & 63;

    // ---- load x row, coalesced float4, conflict-free STS ----
    const float4* xr = (const float4*)(x + (((size_t)(b * 64 + cin)) << 12));
    float4*       xv = (float4*)(xs + 4);
    #pragma unroll
    for (int i = 0; i < 4; i++)
        xv[tid + i * NT] = xr[tid + i * NT];
    if (tid < 4)  { xs[tid] = 0.f; xs[4100 + tid] = 0.f; }
    if (tid < 8)  { sh[tid] = 0.f; sh[2048 + tid] = 0.f;      // idx 0..4 & 2053..2055 persist as S halo
                    dh[tid] = 0.f; dh[2048 + tid] = 0.f; }    // idx 0 & 2049..2051 persist as D halo
    __syncthreads();

    const float ISQ2 = 0.70710678118654752f;

    #pragma unroll 1
    for (int oc = 0; oc < 2; oc++) {
        const int g = 2 * cin + oc;
        float cw[7], wl[7], wh[3];
        #pragma unroll
        for (int k = 0; k < 7; k++) cw[k] = __ldg(&w1[g * 7 + k]);
        #pragma unroll
        for (int k = 0; k < 7; k++) wl[k] = 0.5f * __ldg(&w2L[g * 7 + k]);
        #pragma unroll
        for (int k = 0; k < 3; k++) wh[k] = 0.5f * __ldg(&w2H[g * 3 + k]);
        const float scale = __ldg(&g1[g]) * rsqrtf(__ldg(&v1[g]) + 1e-5f);
        const float shift = __ldg(&b1[g]) - __ldg(&m1[g]) * scale;
        const float wsk   = __ldg(&wskip[g]);

        // ---- stage 1: h = leaky(gelu(bn(conv7))) -> S/D, strided chunks of 4 ----
        #pragma unroll
        for (int i = 0; i < 4; i++) {
            const int c  = tid + i * NT;    // chunk index, lanes contiguous
            const int t0 = 4 * c;
            float w[12];                    // w[j] = xs[t0+j] = x[t0+j-4]
            {
                float4* wv = (float4*)w;
                const float4* p = (const float4*)(xs + t0);  // 16B aligned, 16B lane stride
                wv[0] = p[0]; wv[1] = p[1]; wv[2] = p[2];
            }
            float hv[4];
            #pragma unroll
            for (int j = 0; j < 4; j++) {
                // h[t0+j] taps x[t0+j-3 .. t0+j+3] = w[j+1 .. j+7]
                float a = w[j + 1] * cw[0];
                #pragma unroll
                for (int k = 1; k < 7; k++) a = fmaf(w[j + 1 + k], cw[k], a);
                a = fmaf(a, scale, shift);
                float ge = 0.5f * a * (1.f + erff(a * ISQ2));   // exact gelu
                hv[j] = fmaxf(ge, 0.01f * ge);                   // leaky
            }
            sh[2 * c + 5] = hv[0] + hv[1];
            sh[2 * c + 6] = hv[2] + hv[3];
            dh[2 * c + 1] = hv[0] - hv[1];
            dh[2 * c + 2] = hv[2] - hv[3];
        }
        __syncthreads();

        // ---- stage 2: half-rate convs + merge + skip + leaky ----
        float4* orow = (float4*)(out + (((size_t)(b * 128 + g)) << 12));
        #pragma unroll
        for (int i = 0; i < 4; i++) {
            const int o4 = tid + i * NT;    // output float4 index, lanes contiguous
            const int s0 = 2 * o4;

            float su[8];                    // su[k] = S[s0-3+k]
            {
                float2* v = (float2*)su;
                const float2* p = (const float2*)(sh + s0 + 2);  // 8B aligned, 8B lane stride
                v[0] = p[0]; v[1] = p[1]; v[2] = p[2]; v[3] = p[3];
            }
            float dvv[4];                   // dvv[k] = D[s0-1+k]
            {
                float2* v = (float2*)dvv;
                const float2* p = (const float2*)(dh + s0);
                v[0] = p[0]; v[1] = p[1];
            }
            const float4 xk = *(const float4*)(xs + 4 * o4 + 4);

            float yl0 = su[0] * wl[0], yl1 = su[1] * wl[0];
            #pragma unroll
            for (int k = 1; k < 7; k++) {
                yl0 = fmaf(su[k],     wl[k], yl0);
                yl1 = fmaf(su[k + 1], wl[k], yl1);
            }
            float yh0 = dvv[0] * wh[0], yh1 = dvv[1] * wh[0];
            #pragma unroll
            for (int k = 1; k < 3; k++) {
                yh0 = fmaf(dvv[k],     wh[k], yh0);
                yh1 = fmaf(dvv[k + 1], wh[k], yh1);
            }

            float4 r;
            float v0 = yl0 + yh0 + xk.x * wsk;  r.x = fmaxf(v0, 0.01f * v0);
            float v1 = yl0 - yh0 + xk.y * wsk;  r.y = fmaxf(v1, 0.01f * v1);
            float v2 = yl1 + yh1 + xk.z * wsk;  r.z = fmaxf(v2, 0.01f * v2);
            float v3 = yl1 - yh1 + xk.w * wsk;  r.w = fmaxf(v3, 0.01f * v3);
            orow[o4] = r;                        // perfectly coalesced STG.128
        }
        __syncthreads();
    }
}

extern "C" void kernel_launch(void* const* d_in, const int* in_sizes, int n_in,
                              void* d_out, int out_size)
{
    const float* x     = (const float*)d_in[0];
    const float* w1    = (const float*)d_in[1];
    const float* g1    = (const float*)d_in[2];
    const float* b1    = (const float*)d_in[3];
    const float* m1    = (const float*)d_in[4];
    const float* v1    = (const float*)d_in[5];
    const float* w2L   = (const float*)d_in[6];
    const float* w2H   = (const float*)d_in[7];
    const float* wskip = (const float*)d_in[8];
    float* out = (float*)d_out;

    const int B = in_sizes[0] >> 18;   // elements / (64*4096)
    bw_kernel<<<B * 64, NT>>>(x, w1, g1, b1, m1, v1, w2L, w2H, wskip, out);
}

// round 5
// speedup vs baseline: 1.6048x; 1.0945x over previous
#include <cuda_runtime.h>
#include <math.h>

#define NT 256

// Branchless exact-GELU via Abramowitz-Stegun 7.1.26 erf (|err| <= 1.5e-7),
// fused with leaky-relu. 2 MUFU (RCP, EX2) + ~10 FMA/MUL, zero branches.
__device__ __forceinline__ float gelu_leaky(float a)
{
    const float z = a * 0.70710678118654752f;
    const float x = fabsf(z);
    float d = fmaf(0.3275911f, x, 1.0f);
    float t;
    asm("rcp.approx.f32 %0, %1;" : "=f"(t) : "f"(d));
    float y = fmaf(t, 1.061405429f, -1.453152027f);
    y = fmaf(t, y, 1.421413741f);
    y = fmaf(t, y, -0.284496736f);
    y = fmaf(t, y, 0.254829592f);
    y = y * t;
    const float e = __expf(-x * x);
    float er = fmaf(-y, e, 1.0f);          // erf(|z|)
    er = copysignf(er, a);                 // erf(z)
    const float ha = 0.5f * a;
    const float g = fmaf(ha, er, ha);      // 0.5*a*(1+erf(z))
    return fmaxf(g, 0.01f * g);            // leaky
}

__global__ __launch_bounds__(NT, 4)
void bw_kernel(const float* __restrict__ x,
               const float* __restrict__ w1,
               const float* __restrict__ g1,
               const float* __restrict__ b1,
               const float* __restrict__ m1,
               const float* __restrict__ v1,
               const float* __restrict__ w2L,
               const float* __restrict__ w2H,
               const float* __restrict__ wskip,
               float* __restrict__ out)
{
    // xs[t+4] = x[t], t in [0,4096); zero halo +/-4
    __shared__ __align__(16) float xs[4096 + 16];
    // sh[s+5] = S[s] = h[2s]+h[2s+1]; zero halo, float2 reads aligned+conflict-free
    __shared__ __align__(16) float sh[2064];
    // dh[s+1] = D[s] = h[2s]-h[2s+1]
    __shared__ __align__(16) float dh[2064];

    const int tid = threadIdx.x;
    const int b   = blockIdx.x >> 6;
    const int cin = blockIdx.x & 63;

    // ---- load x row, coalesced float4, conflict-free STS ----
    const float4* xr = (const float4*)(x + (((size_t)(b * 64 + cin)) << 12));
    float4*       xv = (float4*)(xs + 4);
    #pragma unroll
    for (int i = 0; i < 4; i++)
        xv[tid + i * NT] = xr[tid + i * NT];
    if (tid < 4)  { xs[tid] = 0.f; xs[4100 + tid] = 0.f; }
    if (tid < 8)  { sh[tid] = 0.f; sh[2048 + tid] = 0.f;
                    dh[tid] = 0.f; dh[2048 + tid] = 0.f; }
    __syncthreads();

    #pragma unroll 1
    for (int oc = 0; oc < 2; oc++) {
        const int g = 2 * cin + oc;
        float cw[7], wl[7], wh[3];
        #pragma unroll
        for (int k = 0; k < 7; k++) cw[k] = __ldg(&w1[g * 7 + k]);
        #pragma unroll
        for (int k = 0; k < 7; k++) wl[k] = 0.5f * __ldg(&w2L[g * 7 + k]);
        #pragma unroll
        for (int k = 0; k < 3; k++) wh[k] = 0.5f * __ldg(&w2H[g * 3 + k]);
        const float scale = __ldg(&g1[g]) * rsqrtf(__ldg(&v1[g]) + 1e-5f);
        const float shift = __ldg(&b1[g]) - __ldg(&m1[g]) * scale;
        const float wsk   = __ldg(&wskip[g]);

        // ---- stage 1: h = leaky(gelu(bn(conv7))) -> S/D, strided chunks of 4 ----
        #pragma unroll
        for (int i = 0; i < 4; i++) {
            const int c  = tid + i * NT;    // chunk index, lanes contiguous
            const int t0 = 4 * c;
            float w[12];                    // w[j] = xs[t0+j] = x[t0+j-4]
            {
                float4* wv = (float4*)w;
                const float4* p = (const float4*)(xs + t0);  // 16B aligned, conflict-free
                wv[0] = p[0]; wv[1] = p[1]; wv[2] = p[2];
            }
            float hv[4];
            #pragma unroll
            for (int j = 0; j < 4; j++) {
                // h[t0+j] taps x[t0+j-3 .. t0+j+3] = w[j+1 .. j+7]
                float a = w[j + 1] * cw[0];
                #pragma unroll
                for (int k = 1; k < 7; k++) a = fmaf(w[j + 1 + k], cw[k], a);
                a = fmaf(a, scale, shift);
                hv[j] = gelu_leaky(a);
            }
            sh[2 * c + 5] = hv[0] + hv[1];
            sh[2 * c + 6] = hv[2] + hv[3];
            dh[2 * c + 1] = hv[0] - hv[1];
            dh[2 * c + 2] = hv[2] - hv[3];
        }
        __syncthreads();

        // ---- stage 2: half-rate convs + merge + skip + leaky ----
        float4* orow = (float4*)(out + (((size_t)(b * 128 + g)) << 12));
        #pragma unroll
        for (int i = 0; i < 4; i++) {
            const int o4 = tid + i * NT;    // output float4 index, lanes contiguous
            const int s0 = 2 * o4;

            float su[8];                    // su[k] = S[s0-3+k]
            {
                float2* v = (float2*)su;
                const float2* p = (const float2*)(sh + s0 + 2);  // 8B aligned, conflict-free
                v[0] = p[0]; v[1] = p[1]; v[2] = p[2]; v[3] = p[3];
            }
            float dvv[4];                   // dvv[k] = D[s0-1+k]
            {
                float2* v = (float2*)dvv;
                const float2* p = (const float2*)(dh + s0);
                v[0] = p[0]; v[1] = p[1];
            }
            const float4 xk = *(const float4*)(xs + 4 * o4 + 4);

            float yl0 = su[0] * wl[0], yl1 = su[1] * wl[0];
            #pragma unroll
            for (int k = 1; k < 7; k++) {
                yl0 = fmaf(su[k],     wl[k], yl0);
                yl1 = fmaf(su[k + 1], wl[k], yl1);
            }
            float yh0 = dvv[0] * wh[0], yh1 = dvv[1] * wh[0];
            #pragma unroll
            for (int k = 1; k < 3; k++) {
                yh0 = fmaf(dvv[k],     wh[k], yh0);
                yh1 = fmaf(dvv[k + 1], wh[k], yh1);
            }

            float4 r;
            float v0 = yl0 + yh0 + xk.x * wsk;  r.x = fmaxf(v0, 0.01f * v0);
            float v1 = yl0 - yh0 + xk.y * wsk;  r.y = fmaxf(v1, 0.01f * v1);
            float v2 = yl1 + yh1 + xk.z * wsk;  r.z = fmaxf(v2, 0.01f * v2);
            float v3 = yl1 - yh1 + xk.w * wsk;  r.w = fmaxf(v3, 0.01f * v3);
            orow[o4] = r;                        // coalesced STG.128
        }
        __syncthreads();
    }
}

extern "C" void kernel_launch(void* const* d_in, const int* in_sizes, int n_in,
                              void* d_out, int out_size)
{
    const float* x     = (const float*)d_in[0];
    const float* w1    = (const float*)d_in[1];
    const float* g1    = (const float*)d_in[2];
    const float* b1    = (const float*)d_in[3];
    const float* m1    = (const float*)d_in[4];
    const float* v1    = (const float*)d_in[5];
    const float* w2L   = (const float*)d_in[6];
    const float* w2H   = (const float*)d_in[7];
    const float* wskip = (const float*)d_in[8];
    float* out = (float*)d_out;

    const int B = in_sizes[0] >> 18;   // elements / (64*4096)
    bw_kernel<<<B * 64, NT>>>(x, w1, g1, b1, m1, v1, w2L, w2H, wskip, out);
}

// round 7
// speedup vs baseline: 1.7549x; 1.0935x over previous
#include <cuda_runtime.h>
#include <math.h>

#define NT 256

// Branchless exact-GELU via Abramowitz-Stegun 7.1.26 erf (|err| <= 1.5e-7),
// fused with leaky-relu.
__device__ __forceinline__ float gelu_leaky(float a)
{
    const float z = a * 0.70710678118654752f;
    const float x = fabsf(z);
    float d = fmaf(0.3275911f, x, 1.0f);
    float t;
    asm("rcp.approx.f32 %0, %1;" : "=f"(t) : "f"(d));
    float y = fmaf(t, 1.061405429f, -1.453152027f);
    y = fmaf(t, y, 1.421413741f);
    y = fmaf(t, y, -0.284496736f);
    y = fmaf(t, y, 0.254829592f);
    y = y * t;
    const float e = __expf(-x * x);
    float er = fmaf(-y, e, 1.0f);          // erf(|z|)
    er = copysignf(er, a);                 // erf(z)
    const float ha = 0.5f * a;
    const float g = fmaf(ha, er, ha);      // 0.5*a*(1+erf(z))
    return fmaxf(g, 0.01f * g);            // leaky
}

__global__ __launch_bounds__(NT, 4)
void bw_kernel(const float* __restrict__ x,
               const float* __restrict__ w1,
               const float* __restrict__ g1,
               const float* __restrict__ b1,
               const float* __restrict__ m1,
               const float* __restrict__ v1,
               const float* __restrict__ w2L,
               const float* __restrict__ w2H,
               const float* __restrict__ wskip,
               float* __restrict__ out)
{
    // xs[t+4] = x[t]; zero halo both ends
    __shared__ __align__(16) float xs[4096 + 16];
    // sh*[s+4] = S[s] = h[2s]+h[2s+1]  (even offset: float2 STS/LDS aligned, conflict-free)
    // dh*[s+2] = D[s] = h[2s]-h[2s+1]
    __shared__ __align__(16) float sh0[2056], dh0[2056];
    __shared__ __align__(16) float sh1[2056], dh1[2056];

    const int tid = threadIdx.x;
    const int b   = blockIdx.x >> 6;
    const int cin = blockIdx.x & 63;
    const int g0  = 2 * cin, gA = g0 + 1;

    // ---- stage-1 weights for BOTH output channels ----
    float cw0[7], cw1[7];
    #pragma unroll
    for (int k = 0; k < 7; k++) { cw0[k] = __ldg(&w1[g0 * 7 + k]); cw1[k] = __ldg(&w1[gA * 7 + k]); }
    const float sc0 = __ldg(&g1[g0]) * rsqrtf(__ldg(&v1[g0]) + 1e-5f);
    const float sf0 = __ldg(&b1[g0]) - __ldg(&m1[g0]) * sc0;
    const float sc1 = __ldg(&g1[gA]) * rsqrtf(__ldg(&v1[gA]) + 1e-5f);
    const float sf1 = __ldg(&b1[gA]) - __ldg(&m1[gA]) * sc1;

    // ---- load x row (coalesced float4, conflict-free STS) ----
    const float4* xr = (const float4*)(x + (((size_t)(b * 64 + cin)) << 12));
    float4*       xv = (float4*)(xs + 4);
    #pragma unroll
    for (int i = 0; i < 4; i++)
        xv[tid + i * NT] = xr[tid + i * NT];
    if (tid < 4) { xs[tid] = 0.f; xs[4100 + tid] = 0.f; }
    if (tid < 8) {
        sh0[tid] = 0.f; sh0[2048 + tid] = 0.f;   // interior parts rewritten by stage 1
        dh0[tid] = 0.f; dh0[2048 + tid] = 0.f;
        sh1[tid] = 0.f; sh1[2048 + tid] = 0.f;
        dh1[tid] = 0.f; dh1[2048 + tid] = 0.f;
    }
    __syncthreads();

    // ---- stage 1: one x-window load feeds both channels ----
    #pragma unroll
    for (int i = 0; i < 4; i++) {
        const int c  = tid + i * NT;            // chunk index, lanes contiguous
        const int t0 = 4 * c;
        float w[12];                            // w[j] = xs[t0+j]
        {
            float4* wv = (float4*)w;
            const float4* p = (const float4*)(xs + t0);   // 16B aligned, conflict-free
            wv[0] = p[0]; wv[1] = p[1]; wv[2] = p[2];
        }
        // channel 0
        {
            float hv[4];
            #pragma unroll
            for (int j = 0; j < 4; j++) {
                float a = w[j + 1] * cw0[0];
                #pragma unroll
                for (int k = 1; k < 7; k++) a = fmaf(w[j + 1 + k], cw0[k], a);
                a = fmaf(a, sc0, sf0);
                hv[j] = gelu_leaky(a);
            }
            *(float2*)(sh0 + 2 * c + 4) = make_float2(hv[0] + hv[1], hv[2] + hv[3]);
            *(float2*)(dh0 + 2 * c + 2) = make_float2(hv[0] - hv[1], hv[2] - hv[3]);
        }
        // channel 1
        {
            float hv[4];
            #pragma unroll
            for (int j = 0; j < 4; j++) {
                float a = w[j + 1] * cw1[0];
                #pragma unroll
                for (int k = 1; k < 7; k++) a = fmaf(w[j + 1 + k], cw1[k], a);
                a = fmaf(a, sc1, sf1);
                hv[j] = gelu_leaky(a);
            }
            *(float2*)(sh1 + 2 * c + 4) = make_float2(hv[0] + hv[1], hv[2] + hv[3]);
            *(float2*)(dh1 + 2 * c + 2) = make_float2(hv[0] - hv[1], hv[2] - hv[3]);
        }
    }
    __syncthreads();
    asm volatile("" ::: "memory");              // keep stage-2 weight loads down here

    // ---- stage-2 weights ----
    float wl0[7], wl1[7], wh0[3], wh1[3];
    #pragma unroll
    for (int k = 0; k < 7; k++) { wl0[k] = 0.5f * __ldg(&w2L[g0 * 7 + k]); wl1[k] = 0.5f * __ldg(&w2L[gA * 7 + k]); }
    #pragma unroll
    for (int k = 0; k < 3; k++) { wh0[k] = 0.5f * __ldg(&w2H[g0 * 3 + k]); wh1[k] = 0.5f * __ldg(&w2H[gA * 3 + k]); }
    const float wsk0 = __ldg(&wskip[g0]);
    const float wsk1 = __ldg(&wskip[gA]);

    float4* orow0 = (float4*)(out + (((size_t)(b * 128 + g0)) << 12));
    float4* orow1 = (float4*)(out + (((size_t)(b * 128 + gA)) << 12));

    // ---- stage 2: half-rate convs + merge + skip + leaky, both channels ----
    #pragma unroll
    for (int i = 0; i < 4; i++) {
        const int o4 = tid + i * NT;            // output float4 index, lanes contiguous
        const int s0 = 2 * o4;
        const float4 xk = *(const float4*)(xs + 4 * o4 + 4);

        // channel 0
        {
            float a[10], bb[6];
            {
                float2* v = (float2*)a;
                const float2* p = (const float2*)(sh0 + s0);   // aligned, conflict-free
                v[0] = p[0]; v[1] = p[1]; v[2] = p[2]; v[3] = p[3]; v[4] = p[4];
            }
            {
                float2* v = (float2*)bb;
                const float2* p = (const float2*)(dh0 + s0);
                v[0] = p[0]; v[1] = p[1]; v[2] = p[2];
            }
            float yl0 = a[1] * wl0[0], yl1 = a[2] * wl0[0];
            #pragma unroll
            for (int k = 1; k < 7; k++) {
                yl0 = fmaf(a[k + 1], wl0[k], yl0);
                yl1 = fmaf(a[k + 2], wl0[k], yl1);
            }
            float yh0 = bb[1] * wh0[0], yh1 = bb[2] * wh0[0];
            #pragma unroll
            for (int k = 1; k < 3; k++) {
                yh0 = fmaf(bb[k + 1], wh0[k], yh0);
                yh1 = fmaf(bb[k + 2], wh0[k], yh1);
            }
            float4 r;
            float v0 = yl0 + yh0 + xk.x * wsk0;  r.x = fmaxf(v0, 0.01f * v0);
            float v1 = yl0 - yh0 + xk.y * wsk0;  r.y = fmaxf(v1, 0.01f * v1);
            float v2 = yl1 + yh1 + xk.z * wsk0;  r.z = fmaxf(v2, 0.01f * v2);
            float v3 = yl1 - yh1 + xk.w * wsk0;  r.w = fmaxf(v3, 0.01f * v3);
            orow0[o4] = r;
        }
        // channel 1
        {
            float a[10], bb[6];
            {
                float2* v = (float2*)a;
                const float2* p = (const float2*)(sh1 + s0);
                v[0] = p[0]; v[1] = p[1]; v[2] = p[2]; v[3] = p[3]; v[4] = p[4];
            }
            {
                float2* v = (float2*)bb;
                const float2* p = (const float2*)(dh1 + s0);
                v[0] = p[0]; v[1] = p[1]; v[2] = p[2];
            }
            float yl0 = a[1] * wl1[0], yl1 = a[2] * wl1[0];
            #pragma unroll
            for (int k = 1; k < 7; k++) {
                yl0 = fmaf(a[k + 1], wl1[k], yl0);
                yl1 = fmaf(a[k + 2], wl1[k], yl1);
            }
            float yh0 = bb[1] * wh1[0], yh1 = bb[2] * wh1[0];
            #pragma unroll
            for (int k = 1; k < 3; k++) {
                yh0 = fmaf(bb[k + 1], wh1[k], yh0);
                yh1 = fmaf(bb[k + 2], wh1[k], yh1);
            }
            float4 r;
            float v0 = yl0 + yh0 + xk.x * wsk1;  r.x = fmaxf(v0, 0.01f * v0);
            float v1 = yl0 - yh0 + xk.y * wsk1;  r.y = fmaxf(v1, 0.01f * v1);
            float v2 = yl1 + yh1 + xk.z * wsk1;  r.z = fmaxf(v2, 0.01f * v2);
            float v3 = yl1 - yh1 + xk.w * wsk1;  r.w = fmaxf(v3, 0.01f * v3);
            orow1[o4] = r;
        }
    }
}

extern "C" void kernel_launch(void* const* d_in, const int* in_sizes, int n_in,
                              void* d_out, int out_size)
{
    const float* x     = (const float*)d_in[0];
    const float* w1    = (const float*)d_in[1];
    const float* g1    = (const float*)d_in[2];
    const float* b1    = (const float*)d_in[3];
    const float* m1    = (const float*)d_in[4];
    const float* v1    = (const float*)d_in[5];
    const float* w2L   = (const float*)d_in[6];
    const float* w2H   = (const float*)d_in[7];
    const float* wskip = (const float*)d_in[8];
    float* out = (float*)d_out;

    const int B = in_sizes[0] >> 18;   // elements / (64*4096)
    bw_kernel<<<B * 64, NT>>>(x, w1, g1, b1, m1, v1, w2L, w2H, wskip, out);
}